// round 1
// baseline (speedup 1.0000x reference)
#include <cuda_runtime.h>
#include <cuda_bf16.h>

// GraphSAGE: N=100000 nodes, E=1600000 edges, 64 -> 128 -> 128 -> 64
// Pipeline:
//   deg/agg1 scatter -> layer1 GEMM(relu) -> agg2 scatter -> layer2 GEMM(relu)
//   -> mlp1 GEMM(relu) -> mlp2 GEMM
//
// Inputs (metadata order):
//  0 features [N,64] f32
//  1 W_neigh1 [64,128]
//  2 W_self1  [64,128]
//  3 b1       [128]
//  4 W_neigh2 [128,128]
//  5 W_self2  [128,128]
//  6 b2       [128]
//  7 Wm1      [128,128]
//  8 bm1      [128]
//  9 Wm2      [128,64]
// 10 bm2      [64]
// 11 src      [E] int32 or int64
// 12 dst      [E] int32 or int64
// output: [N,64] f32

#define NN 100000
#define EE 1600000
#define INF 64
#define HID 128
#define OUTF 64

// ---------------- scratch (device globals; no allocation allowed) ----------
__device__ float g_agg1[(size_t)NN * INF];     // 25.6 MB
__device__ float g_x1[(size_t)NN * HID];       // 51.2 MB
__device__ float g_agg2[(size_t)NN * HID];     // 51.2 MB
__device__ float g_x2[(size_t)NN * HID];       // 51.2 MB
__device__ float g_x3[(size_t)NN * HID];       // 51.2 MB
__device__ float g_deg[NN];
__device__ float g_invdeg[NN];
__device__ int   g_flag64;

// ---------------- helpers --------------------------------------------------
__device__ __forceinline__ int ld_idx(const void* p, int i, int f64) {
    if (f64) return (int)((const long long*)p)[i];
    return ((const int*)p)[i];
}

// Detect whether src indices are stored as int64 (odd int32 halves all zero)
// or int32. Values are in [0, 100000), so the high 32 bits of int64 entries
// are always 0, while for int32 storage the odd positions are real indices
// (P[all 64 are 0] ~ (1e-5)^64 ~ 0).
__global__ void detect_kernel(const void* src) {
    if (blockIdx.x == 0 && threadIdx.x == 0) {
        const int* p = (const int*)src;
        int ok64 = 1;
        for (int i = 0; i < 64; i++)
            if (p[2 * i + 1] != 0) ok64 = 0;
        g_flag64 = ok64;
    }
}

__global__ void zero_kernel(float4* p, int n4) {
    int i = blockIdx.x * blockDim.x + threadIdx.x;
    if (i < n4) p[i] = make_float4(0.f, 0.f, 0.f, 0.f);
}

// ---------------- aggregation scatters -------------------------------------
// One thread per (edge, 16B chunk). Gather from features[src], atomic-add
// into agg1[dst]. Chunk 0 also counts degree.
__global__ void scatter1_kernel(const float4* __restrict__ feat4,
                                const void* __restrict__ src,
                                const void* __restrict__ dst,
                                float* __restrict__ agg1,
                                float* __restrict__ deg) {
    int i = blockIdx.x * blockDim.x + threadIdx.x;
    if (i >= EE * 16) return;
    int e = i >> 4;
    int c = i & 15;
    int f64 = g_flag64;
    int s = ld_idx(src, e, f64);
    int d = ld_idx(dst, e, f64);
    float4 v = feat4[s * 16 + c];
    float* o = agg1 + d * INF + c * 4;
    atomicAdd(o + 0, v.x);
    atomicAdd(o + 1, v.y);
    atomicAdd(o + 2, v.z);
    atomicAdd(o + 3, v.w);
    if (c == 0) atomicAdd(&deg[d], 1.0f);
}

// One thread per (edge, 16B chunk of 128 floats = 32 chunks)
__global__ void scatter2_kernel(const float4* __restrict__ x4,
                                const void* __restrict__ src,
                                const void* __restrict__ dst,
                                float* __restrict__ agg2) {
    int i = blockIdx.x * blockDim.x + threadIdx.x;
    if (i >= EE * 32) return;
    int e = i >> 5;
    int c = i & 31;
    int f64 = g_flag64;
    int s = ld_idx(src, e, f64);
    int d = ld_idx(dst, e, f64);
    float4 v = x4[s * 32 + c];
    float* o = agg2 + d * HID + c * 4;
    atomicAdd(o + 0, v.x);
    atomicAdd(o + 1, v.y);
    atomicAdd(o + 2, v.z);
    atomicAdd(o + 3, v.w);
}

__global__ void invdeg_kernel(const float* __restrict__ deg,
                              float* __restrict__ invdeg) {
    int i = blockIdx.x * blockDim.x + threadIdx.x;
    if (i < NN) invdeg[i] = 1.0f / fmaxf(deg[i], 1.0f);
}

// ---------------- fused dense layer ----------------------------------------
// out[m, :] = act( X[m,:KIN] @ Ws + (AGG[m,:KIN]*invdeg[m]) @ Wn + bias )
// Whole K resident in shared; 64-row tiles; 256 threads; each thread owns an
// RPT x 4 microtile (register blocked). W rows read as float4, X broadcast.
template <int KIN, int NOUT, bool NEIGH, bool RELU>
__global__ void dense_kernel(const float* __restrict__ X,
                             const float* __restrict__ AGG,
                             const float* __restrict__ invdeg,
                             const float* __restrict__ Ws,
                             const float* __restrict__ Wn,
                             const float* __restrict__ bias,
                             float* __restrict__ out,
                             int nrows) {
    constexpr int KT  = NEIGH ? 2 * KIN : KIN;
    constexpr int TM  = 64;
    constexpr int CT  = NOUT / 4;        // col-thread groups
    constexpr int RT  = 256 / CT;        // row-thread groups
    constexpr int RPT = TM / RT;         // rows per thread

    extern __shared__ float sh[];
    float* Wsh = sh;                 // [KT][NOUT]
    float* Xsh = sh + KT * NOUT;     // [TM][KT]

    const int tid    = threadIdx.x;
    const int m_base = blockIdx.x * TM;

    // stage weights
    for (int i = tid; i < KIN * NOUT; i += 256) Wsh[i] = Ws[i];
    if (NEIGH)
        for (int i = tid; i < KIN * NOUT; i += 256) Wsh[KIN * NOUT + i] = Wn[i];

    // stage X tile (self part)
    for (int i = tid; i < TM * KIN; i += 256) {
        int m = i / KIN, k = i % KIN;
        int gm = m_base + m;
        Xsh[m * KT + k] = (gm < nrows) ? X[(size_t)gm * KIN + k] : 0.f;
    }
    // stage neighbor part (mean = agg * invdeg)
    if (NEIGH) {
        for (int i = tid; i < TM * KIN; i += 256) {
            int m = i / KIN, k = i % KIN;
            int gm = m_base + m;
            Xsh[m * KT + KIN + k] =
                (gm < nrows) ? AGG[(size_t)gm * KIN + k] * invdeg[gm] : 0.f;
        }
    }
    __syncthreads();

    const int ct = tid % CT;
    const int rt = tid / CT;
    const int j0 = ct * 4;
    const int m0 = rt * RPT;

    float acc[RPT][4];
    float4 bv = *(const float4*)(bias + j0);
#pragma unroll
    for (int r = 0; r < RPT; r++) {
        acc[r][0] = bv.x; acc[r][1] = bv.y; acc[r][2] = bv.z; acc[r][3] = bv.w;
    }

#pragma unroll 4
    for (int k = 0; k < KT; k++) {
        float4 w = *(const float4*)(Wsh + k * NOUT + j0);
#pragma unroll
        for (int r = 0; r < RPT; r++) {
            float xv = Xsh[(m0 + r) * KT + k];
            acc[r][0] += xv * w.x;
            acc[r][1] += xv * w.y;
            acc[r][2] += xv * w.z;
            acc[r][3] += xv * w.w;
        }
    }

#pragma unroll
    for (int r = 0; r < RPT; r++) {
        int gm = m_base + m0 + r;
        if (gm < nrows) {
            float4 v;
            v.x = RELU ? fmaxf(acc[r][0], 0.f) : acc[r][0];
            v.y = RELU ? fmaxf(acc[r][1], 0.f) : acc[r][1];
            v.z = RELU ? fmaxf(acc[r][2], 0.f) : acc[r][2];
            v.w = RELU ? fmaxf(acc[r][3], 0.f) : acc[r][3];
            *(float4*)(out + (size_t)gm * NOUT + j0) = v;
        }
    }
}

// ---------------- launch ----------------------------------------------------
extern "C" void kernel_launch(void* const* d_in, const int* in_sizes, int n_in,
                              void* d_out, int out_size) {
    const float* features = (const float*)d_in[0];
    const float* W_neigh1 = (const float*)d_in[1];
    const float* W_self1  = (const float*)d_in[2];
    const float* b1       = (const float*)d_in[3];
    const float* W_neigh2 = (const float*)d_in[4];
    const float* W_self2  = (const float*)d_in[5];
    const float* b2       = (const float*)d_in[6];
    const float* Wm1      = (const float*)d_in[7];
    const float* bm1      = (const float*)d_in[8];
    const float* Wm2      = (const float*)d_in[9];
    const float* bm2      = (const float*)d_in[10];
    const void*  src      = d_in[11];
    const void*  dst      = d_in[12];
    float* out = (float*)d_out;

    float *agg1, *x1, *agg2, *x2, *x3, *deg, *invdeg;
    cudaGetSymbolAddress((void**)&agg1,   g_agg1);
    cudaGetSymbolAddress((void**)&x1,     g_x1);
    cudaGetSymbolAddress((void**)&agg2,   g_agg2);
    cudaGetSymbolAddress((void**)&x2,     g_x2);
    cudaGetSymbolAddress((void**)&x3,     g_x3);
    cudaGetSymbolAddress((void**)&deg,    g_deg);
    cudaGetSymbolAddress((void**)&invdeg, g_invdeg);

    // opt-in shared memory sizes
    const int sh_l1   = (2 * INF * HID + 64 * 2 * INF) * 4;   // 98304
    const int sh_l2   = (2 * HID * HID + 64 * 2 * HID) * 4;   // 196608
    const int sh_m1   = (HID * HID + 64 * HID) * 4;           // 98304
    const int sh_m2   = (HID * OUTF + 64 * HID) * 4;          // 65536
    cudaFuncSetAttribute(dense_kernel<INF, HID, true,  true >,
                         cudaFuncAttributeMaxDynamicSharedMemorySize, sh_l1);
    cudaFuncSetAttribute(dense_kernel<HID, HID, true,  true >,
                         cudaFuncAttributeMaxDynamicSharedMemorySize, sh_l2);
    cudaFuncSetAttribute(dense_kernel<HID, HID, false, true >,
                         cudaFuncAttributeMaxDynamicSharedMemorySize, sh_m1);
    cudaFuncSetAttribute(dense_kernel<HID, OUTF, false, false>,
                         cudaFuncAttributeMaxDynamicSharedMemorySize, sh_m2);

    detect_kernel<<<1, 32>>>(src);

    // zero agg1, agg2, deg
    zero_kernel<<<(NN * 16 + 255) / 256, 256>>>((float4*)agg1, NN * 16);
    zero_kernel<<<(NN * 32 + 255) / 256, 256>>>((float4*)agg2, NN * 32);
    zero_kernel<<<(NN / 4 + 255) / 256, 256>>>((float4*)deg, NN / 4);

    // layer 1 aggregation
    scatter1_kernel<<<(EE * 16 + 255) / 256, 256>>>(
        (const float4*)features, src, dst, agg1, deg);
    invdeg_kernel<<<(NN + 255) / 256, 256>>>(deg, invdeg);

    const int gblocks = (NN + 63) / 64;
    // layer 1 dense
    dense_kernel<INF, HID, true, true><<<gblocks, 256, sh_l1>>>(
        features, agg1, invdeg, W_self1, W_neigh1, b1, x1, NN);

    // layer 2 aggregation
    scatter2_kernel<<<(EE * 32 + 255) / 256, 256>>>(
        (const float4*)x1, src, dst, agg2);

    // layer 2 dense
    dense_kernel<HID, HID, true, true><<<gblocks, 256, sh_l2>>>(
        x1, agg2, invdeg, W_self2, W_neigh2, b2, x2, NN);

    // MLP
    dense_kernel<HID, HID, false, true><<<gblocks, 256, sh_m1>>>(
        x2, nullptr, nullptr, Wm1, nullptr, bm1, x3, NN);
    dense_kernel<HID, OUTF, false, false><<<gblocks, 256, sh_m2>>>(
        x3, nullptr, nullptr, Wm2, nullptr, bm2, out, NN);
}

// round 2
// speedup vs baseline: 1.4224x; 1.4224x over previous
#include <cuda_runtime.h>
#include <cuda_bf16.h>

// GraphSAGE: N=100000 nodes, E=1600000 edges, 64 -> 128 -> 128 -> 64
// R2: CSR-based gather-mean aggregation (no fp32 atomics), then dense GEMMs.
//
// Inputs (metadata order):
//  0 features [N,64] f32
//  1 W_neigh1 [64,128]   2 W_self1 [64,128]   3 b1 [128]
//  4 W_neigh2 [128,128]  5 W_self2 [128,128]  6 b2 [128]
//  7 Wm1 [128,128]  8 bm1 [128]  9 Wm2 [128,64] 10 bm2 [64]
// 11 src [E] int32/int64   12 dst [E] int32/int64
// output: [N,64] f32

#define NN 100000
#define EE 1600000
#define INF 64
#define HID 128
#define OUTF 64

// ---------------- scratch (device globals; no allocation allowed) ----------
__device__ float g_agg1[(size_t)NN * INF];     // mean-aggregated features
__device__ float g_x1[(size_t)NN * HID];
__device__ float g_agg2[(size_t)NN * HID];
__device__ float g_x2[(size_t)NN * HID];
__device__ float g_x3[(size_t)NN * HID];
__device__ float g_invdeg[NN];
__device__ int   g_cnt[NN];
__device__ int   g_cursor[NN];
__device__ int   g_off[NN + 1];
__device__ int   g_csr[EE];
__device__ int   g_flag64;

// ---------------- helpers --------------------------------------------------
__device__ __forceinline__ int ld_idx(const void* p, int i, int f64) {
    if (f64) return (int)((const long long*)p)[i];
    return ((const int*)p)[i];
}

// int64 vs int32 storage detection: node ids < 100000 so high halves of int64
// entries are all zero; for int32 storage the odd int32 slots are real ids.
__global__ void detect_kernel(const void* src) {
    if (blockIdx.x == 0 && threadIdx.x == 0) {
        const int* p = (const int*)src;
        int ok64 = 1;
        for (int i = 0; i < 64; i++)
            if (p[2 * i + 1] != 0) ok64 = 0;
        g_flag64 = ok64;
    }
}

__global__ void zero2_int_kernel(int* a, int* b, int n) {
    int i = blockIdx.x * blockDim.x + threadIdx.x;
    if (i < n) { a[i] = 0; b[i] = 0; }
}

// ---------------- CSR build -------------------------------------------------
__global__ void hist_kernel(const void* __restrict__ dst,
                            int* __restrict__ cnt) {
    int e = blockIdx.x * blockDim.x + threadIdx.x;
    if (e >= EE) return;
    int d = ld_idx(dst, e, g_flag64);
    atomicAdd(&cnt[d], 1);
}

// Single-block exclusive scan of cnt -> off, plus invdeg.
__global__ void scan_kernel(const int* __restrict__ cnt,
                            int* __restrict__ off,
                            float* __restrict__ invdeg) {
    const int T = 1024;
    const int CH = (NN + T - 1) / T;  // 98
    __shared__ int partial[T];
    int t = threadIdx.x;
    int begin = t * CH;
    int end = min(begin + CH, NN);

    int s = 0;
    for (int i = begin; i < end; i++) s += cnt[i];
    partial[t] = s;
    __syncthreads();

    // inclusive Hillis-Steele scan
    for (int d = 1; d < T; d <<= 1) {
        int v = (t >= d) ? partial[t - d] : 0;
        __syncthreads();
        partial[t] += v;
        __syncthreads();
    }
    int run = (t == 0) ? 0 : partial[t - 1];
    __syncthreads();

    for (int i = begin; i < end; i++) {
        off[i] = run;
        int c = cnt[i];
        invdeg[i] = 1.0f / fmaxf((float)c, 1.0f);
        run += c;
    }
    if (t == T - 1) off[NN] = run;
}

__global__ void fill_kernel(const void* __restrict__ src,
                            const void* __restrict__ dst,
                            const int* __restrict__ off,
                            int* __restrict__ cursor,
                            int* __restrict__ csr) {
    int e = blockIdx.x * blockDim.x + threadIdx.x;
    if (e >= EE) return;
    int f64 = g_flag64;
    int s = ld_idx(src, e, f64);
    int d = ld_idx(dst, e, f64);
    int pos = off[d] + atomicAdd(&cursor[d], 1);
    csr[pos] = s;
}

// ---------------- gather-mean ----------------------------------------------
// One warp per node; lanes cover the feature row; 2-way unrolled neighbor loop.
__global__ void gather64_kernel(const float2* __restrict__ X2,
                                const int* __restrict__ csr,
                                const int* __restrict__ off,
                                const float* __restrict__ invdeg,
                                float2* __restrict__ out2) {
    int w = (blockIdx.x * blockDim.x + threadIdx.x) >> 5;
    int lane = threadIdx.x & 31;
    if (w >= NN) return;
    int beg = off[w], end = off[w + 1];
    float2 a0 = make_float2(0.f, 0.f);
    float2 a1 = make_float2(0.f, 0.f);
    int j = beg;
    for (; j + 1 < end; j += 2) {
        int s0 = csr[j], s1 = csr[j + 1];
        float2 v0 = X2[(size_t)s0 * 32 + lane];
        float2 v1 = X2[(size_t)s1 * 32 + lane];
        a0.x += v0.x; a0.y += v0.y;
        a1.x += v1.x; a1.y += v1.y;
    }
    if (j < end) {
        int s0 = csr[j];
        float2 v0 = X2[(size_t)s0 * 32 + lane];
        a0.x += v0.x; a0.y += v0.y;
    }
    float inv = invdeg[w];
    out2[(size_t)w * 32 + lane] =
        make_float2((a0.x + a1.x) * inv, (a0.y + a1.y) * inv);
}

__global__ void gather128_kernel(const float4* __restrict__ X4,
                                 const int* __restrict__ csr,
                                 const int* __restrict__ off,
                                 const float* __restrict__ invdeg,
                                 float4* __restrict__ out4) {
    int w = (blockIdx.x * blockDim.x + threadIdx.x) >> 5;
    int lane = threadIdx.x & 31;
    if (w >= NN) return;
    int beg = off[w], end = off[w + 1];
    float4 a0 = make_float4(0.f, 0.f, 0.f, 0.f);
    float4 a1 = make_float4(0.f, 0.f, 0.f, 0.f);
    int j = beg;
    for (; j + 1 < end; j += 2) {
        int s0 = csr[j], s1 = csr[j + 1];
        float4 v0 = X4[(size_t)s0 * 32 + lane];
        float4 v1 = X4[(size_t)s1 * 32 + lane];
        a0.x += v0.x; a0.y += v0.y; a0.z += v0.z; a0.w += v0.w;
        a1.x += v1.x; a1.y += v1.y; a1.z += v1.z; a1.w += v1.w;
    }
    if (j < end) {
        int s0 = csr[j];
        float4 v0 = X4[(size_t)s0 * 32 + lane];
        a0.x += v0.x; a0.y += v0.y; a0.z += v0.z; a0.w += v0.w;
    }
    float inv = invdeg[w];
    out4[(size_t)w * 32 + lane] =
        make_float4((a0.x + a1.x) * inv, (a0.y + a1.y) * inv,
                    (a0.z + a1.z) * inv, (a0.w + a1.w) * inv);
}

// ---------------- fused dense layer ----------------------------------------
// out[m,:] = act( [X | AGG][m,:] @ [[Ws],[Wn]] + bias );  AGG already the mean.
template <int KIN, int NOUT, bool NEIGH, bool RELU>
__global__ void dense_kernel(const float* __restrict__ X,
                             const float* __restrict__ AGG,
                             const float* __restrict__ Ws,
                             const float* __restrict__ Wn,
                             const float* __restrict__ bias,
                             float* __restrict__ out,
                             int nrows) {
    constexpr int KT  = NEIGH ? 2 * KIN : KIN;
    constexpr int TM  = 64;
    constexpr int CT  = NOUT / 4;
    constexpr int RT  = 256 / CT;
    constexpr int RPT = TM / RT;

    extern __shared__ float sh[];
    float* Wsh = sh;                 // [KT][NOUT]
    float* Xsh = sh + KT * NOUT;     // [TM][KT]

    const int tid    = threadIdx.x;
    const int m_base = blockIdx.x * TM;

    for (int i = tid; i < KIN * NOUT; i += 256) Wsh[i] = Ws[i];
    if (NEIGH)
        for (int i = tid; i < KIN * NOUT; i += 256) Wsh[KIN * NOUT + i] = Wn[i];

    for (int i = tid; i < TM * KIN; i += 256) {
        int m = i / KIN, k = i % KIN;
        int gm = m_base + m;
        Xsh[m * KT + k] = (gm < nrows) ? X[(size_t)gm * KIN + k] : 0.f;
    }
    if (NEIGH) {
        for (int i = tid; i < TM * KIN; i += 256) {
            int m = i / KIN, k = i % KIN;
            int gm = m_base + m;
            Xsh[m * KT + KIN + k] =
                (gm < nrows) ? AGG[(size_t)gm * KIN + k] : 0.f;
        }
    }
    __syncthreads();

    const int ct = tid % CT;
    const int rt = tid / CT;
    const int j0 = ct * 4;
    const int m0 = rt * RPT;

    float acc[RPT][4];
    float4 bv = *(const float4*)(bias + j0);
#pragma unroll
    for (int r = 0; r < RPT; r++) {
        acc[r][0] = bv.x; acc[r][1] = bv.y; acc[r][2] = bv.z; acc[r][3] = bv.w;
    }

#pragma unroll 4
    for (int k = 0; k < KT; k++) {
        float4 w = *(const float4*)(Wsh + k * NOUT + j0);
#pragma unroll
        for (int r = 0; r < RPT; r++) {
            float xv = Xsh[(m0 + r) * KT + k];
            acc[r][0] += xv * w.x;
            acc[r][1] += xv * w.y;
            acc[r][2] += xv * w.z;
            acc[r][3] += xv * w.w;
        }
    }

#pragma unroll
    for (int r = 0; r < RPT; r++) {
        int gm = m_base + m0 + r;
        if (gm < nrows) {
            float4 v;
            v.x = RELU ? fmaxf(acc[r][0], 0.f) : acc[r][0];
            v.y = RELU ? fmaxf(acc[r][1], 0.f) : acc[r][1];
            v.z = RELU ? fmaxf(acc[r][2], 0.f) : acc[r][2];
            v.w = RELU ? fmaxf(acc[r][3], 0.f) : acc[r][3];
            *(float4*)(out + (size_t)gm * NOUT + j0) = v;
        }
    }
}

// ---------------- launch ----------------------------------------------------
extern "C" void kernel_launch(void* const* d_in, const int* in_sizes, int n_in,
                              void* d_out, int out_size) {
    const float* features = (const float*)d_in[0];
    const float* W_neigh1 = (const float*)d_in[1];
    const float* W_self1  = (const float*)d_in[2];
    const float* b1       = (const float*)d_in[3];
    const float* W_neigh2 = (const float*)d_in[4];
    const float* W_self2  = (const float*)d_in[5];
    const float* b2       = (const float*)d_in[6];
    const float* Wm1      = (const float*)d_in[7];
    const float* bm1      = (const float*)d_in[8];
    const float* Wm2      = (const float*)d_in[9];
    const float* bm2      = (const float*)d_in[10];
    const void*  src      = d_in[11];
    const void*  dst      = d_in[12];
    float* out = (float*)d_out;

    float *agg1, *x1, *agg2, *x2, *x3, *invdeg;
    int *cnt, *cursor, *off, *csr;
    cudaGetSymbolAddress((void**)&agg1,   g_agg1);
    cudaGetSymbolAddress((void**)&x1,     g_x1);
    cudaGetSymbolAddress((void**)&agg2,   g_agg2);
    cudaGetSymbolAddress((void**)&x2,     g_x2);
    cudaGetSymbolAddress((void**)&x3,     g_x3);
    cudaGetSymbolAddress((void**)&invdeg, g_invdeg);
    cudaGetSymbolAddress((void**)&cnt,    g_cnt);
    cudaGetSymbolAddress((void**)&cursor, g_cursor);
    cudaGetSymbolAddress((void**)&off,    g_off);
    cudaGetSymbolAddress((void**)&csr,    g_csr);

    const int sh_l1 = (2 * INF * HID + 64 * 2 * INF) * 4;   // 98304
    const int sh_l2 = (2 * HID * HID + 64 * 2 * HID) * 4;   // 196608
    const int sh_m1 = (HID * HID + 64 * HID) * 4;           // 98304
    const int sh_m2 = (HID * OUTF + 64 * HID) * 4;          // 65536
    cudaFuncSetAttribute(dense_kernel<INF, HID, true,  true >,
                         cudaFuncAttributeMaxDynamicSharedMemorySize, sh_l1);
    cudaFuncSetAttribute(dense_kernel<HID, HID, true,  true >,
                         cudaFuncAttributeMaxDynamicSharedMemorySize, sh_l2);
    cudaFuncSetAttribute(dense_kernel<HID, HID, false, true >,
                         cudaFuncAttributeMaxDynamicSharedMemorySize, sh_m1);
    cudaFuncSetAttribute(dense_kernel<HID, OUTF, false, false>,
                         cudaFuncAttributeMaxDynamicSharedMemorySize, sh_m2);

    detect_kernel<<<1, 32>>>(src);

    // CSR build
    zero2_int_kernel<<<(NN + 255) / 256, 256>>>(cnt, cursor, NN);
    hist_kernel<<<(EE + 255) / 256, 256>>>(dst, cnt);
    scan_kernel<<<1, 1024>>>(cnt, off, invdeg);
    fill_kernel<<<(EE + 255) / 256, 256>>>(src, dst, off, cursor, csr);

    // layer 1: gather-mean + dense
    gather64_kernel<<<(NN * 32 + 255) / 256, 256>>>(
        (const float2*)features, csr, off, invdeg, (float2*)agg1);
    const int gblocks = (NN + 63) / 64;
    dense_kernel<INF, HID, true, true><<<gblocks, 256, sh_l1>>>(
        features, agg1, W_self1, W_neigh1, b1, x1, NN);

    // layer 2: gather-mean + dense
    gather128_kernel<<<(NN * 32 + 255) / 256, 256>>>(
        (const float4*)x1, csr, off, invdeg, (float4*)agg2);
    dense_kernel<HID, HID, true, true><<<gblocks, 256, sh_l2>>>(
        x1, agg2, W_self2, W_neigh2, b2, x2, NN);

    // MLP
    dense_kernel<HID, HID, false, true><<<gblocks, 256, sh_m1>>>(
        x2, nullptr, Wm1, nullptr, bm1, x3, NN);
    dense_kernel<HID, OUTF, false, false><<<gblocks, 256, sh_m2>>>(
        x3, nullptr, Wm2, nullptr, bm2, out, NN);
}